// round 15
// baseline (speedup 1.0000x reference)
#include <cuda_runtime.h>
#include <cuda_fp16.h>
#include <math.h>

#define Bz 64
#define Tz 128
#define Sz 100
typedef unsigned int u32; typedef unsigned short u16;

// ---- LSTM mma config (fp16, 64-row CTAs, LDS.128 B, half2 epilogue) ----
#define OB 0                 // B image: 480 n * 320B = 153600
#define OA0 153600           // A buf0: 4 mtile * 9 ks * 512B = 18432
#define OA1 172032           // A buf1
#define OBIAS 190464         // 480 floats
#define OWL 192384           // 120 floats
#define SMEMT 192960
#define ABUF 18432
// MLP1
#define KCH 40
#define NCHUNK 250

__device__ u16   g_Bpack[480 * 160];       // [n][160] fp16 weights, ks-paired layout
__device__ float g_biasT[480];             // [n] bias per gate col
__device__ float g_W2t[10000 * 256];
__device__ float g_spart[4 * 6400];        // [nh][row]
__device__ float g_foo[Bz * Sz * Sz];
__device__ float g_part[NCHUNK * Bz * 256];
__device__ float g_part2[10 * Bz * 256];
__device__ float g_z1[Bz * 256];

__device__ __forceinline__ u16 h2u(float v){
    __half hh = __float2half_rn(v);
    return *reinterpret_cast<u16*>(&hh);
}
__device__ __forceinline__ __half2 tanh2(__half2 x){
    u32 xi = *reinterpret_cast<u32*>(&x), yo;
    asm("tanh.approx.f16x2 %0, %1;" : "=r"(yo) : "r"(xi));
    return *reinterpret_cast<__half2*>(&yo);
}
__device__ __forceinline__ u32 h2raw(__half2 x){ return *reinterpret_cast<u32*>(&x); }
__device__ __forceinline__ __half2 raw2h(u32 x){ return *reinterpret_cast<__half2*>(&x); }

#define MMAOP(d, a, b0, b1) asm volatile( \
    "mma.sync.aligned.m16n8k16.row.col.f32.f16.f16.f32 {%0,%1,%2,%3},{%4,%5,%6,%7},{%8,%9},{%0,%1,%2,%3};" \
    : "+f"((d)[0]), "+f"((d)[1]), "+f"((d)[2]), "+f"((d)[3]) \
    : "r"((a).x),"r"((a).y),"r"((a).z),"r"((a).w), "r"(b0),"r"(b1))

// ---------------- prep: B pack (ks-paired, LDS.128-friendly) + bias ----------------
__global__ void prep_kernel(const float* __restrict__ Wih, const float* __restrict__ Whh,
                            const float* __restrict__ bih, const float* __restrict__ bhh) {
    int idx = blockIdx.x * blockDim.x + threadIdx.x, stride = gridDim.x * blockDim.x;
    for (int i = idx; i < 480 * 144; i += stride) {
        int k = i % 144, n = i / 144;
        int g = n & 3, c = n >> 2;           // cell 0..119
        int j = g * 120 + c;
        float v = 0.f;
        if (k < 16) v = Wih[j * 16 + k];
        else if (k < 136) v = Whh[j * 120 + (k - 16)];
        int ks = k >> 4, kl = k & 15;
        int q = (kl & 7) >> 1;
        int pos = q * 40 + (ks >> 1) * 8 + (ks & 1) * 4 + ((kl >> 3) & 1) * 2 + (kl & 1);
        g_Bpack[(size_t)n * 160 + pos] = h2u(v);
    }
    for (int i = idx; i < 480; i += stride) {
        int j = (i & 3) * 120 + (i >> 2);
        g_biasT[i] = bih[j] + bhh[j];
    }
}

// ---------------- W2 transpose, smem-tiled ----------------
__global__ void w2t_kernel(const float* __restrict__ W2) {
    __shared__ float tile[32][33];
    int k0 = blockIdx.x * 32, o0 = blockIdx.y * 32;
    int tx = threadIdx.x, ty = threadIdx.y;
    int k = k0 + tx, o = o0 + ty;
    if (k < 10000) tile[ty][tx] = W2[(size_t)o * 10000 + k];
    __syncthreads();
    int kk = k0 + ty, oo = o0 + tx;
    if (kk < 10000) g_W2t[(size_t)kk * 256 + oo] = tile[tx][ty];
}

// ---------------- warp-MMA LSTM ----------------
__device__ __forceinline__ void write_x(char* sm, u32 abase, int tid, float4 v0, float4 v1) {
    int lr = tid >> 1;                       // row 0..63
    float xv[8] = {v0.x, v0.y, v0.z, v0.w, v1.x, v1.y, v1.z, v1.w};
    u32 base = abase + (u32)((lr >> 4) * 9) * 512;
    #pragma unroll
    for (int j = 0; j < 4; j++) {
        int k = (tid & 1) * 8 + 2 * j;
        u32 off = base + (u32)(((lr & 7) * 4 + ((k & 7) >> 1)) * 16 + (((k >> 3) & 1) * 2 + ((lr >> 3) & 1)) * 4);
        *(u32*)(sm + off) = (u32)h2u(xv[2*j]) | ((u32)h2u(xv[2*j+1]) << 16);
    }
}

__global__ void __launch_bounds__(256, 1)
lstm_mma(const float* __restrict__ x, const float* __restrict__ w_lin) {
    extern __shared__ char sm[];
    const int tid = threadIdx.x, w = tid >> 5, lane = tid & 31;
    const int q = lane & 3, rq = lane >> 2;
    const int wm = w & 1;         // mtile pair {wm, wm+2}
    const int nh = w >> 1;        // nf quarter (0..3), 15 nf each
    const bool even = !(q & 1);
    const int row0 = blockIdx.x * 64;
    const bool xact = tid < 128;  // 2 threads per row for x staging
    const int lr = tid >> 1;
    const int xrow = row0 + (xact ? lr : 0);
    const int xb = xrow / Sz, xs = xrow - xb * Sz;
    const float* xrowp = x + ((size_t)xb * Tz * Sz + xs) * 16 + (tid & 1) * 8;

    // init: B copy, A zero (both bufs), bias, w_lin
    {
        const int4* src = (const int4*)g_Bpack;
        int4* dst = (int4*)sm;
        for (int i = tid; i < 153600 / 16; i += 256) dst[i] = src[i];
        int4 z = {0, 0, 0, 0};
        for (int i = tid; i < (2 * ABUF) / 16; i += 256) ((int4*)(sm + OA0))[i] = z;
        if (tid < 240) {
            ((float*)(sm + OBIAS))[tid] = g_biasT[tid];
            ((float*)(sm + OBIAS))[tid + 240] = g_biasT[tid + 240];
        }
        if (tid < 120) ((float*)(sm + OWL))[tid] = w_lin[tid];
    }
    __syncthreads();
    if (xact) {
        float4 v0 = *(const float4*)(xrowp);
        float4 v1 = *(const float4*)(xrowp + 4);
        write_x(sm, OA0, tid, v0, v1);
    }
    __syncthreads();

    const float* wl = (const float*)(sm + OWL);
    const float* bias = (const float*)(sm + OBIAS);
    const char* Bp = sm + rq * 320 + q * 80;   // n-row 320B, q-stride 80B

    const __half2 c05 = __float2half2_rn(0.5f);
    __half2 cst2[15];
    #pragma unroll
    for (int i = 0; i < 15; i++) cst2[i] = __float2half2_rn(0.f);
    float sacc0 = 0.f, sacc1 = 0.f;

    for (int t = 0; t < Tz; ++t) {
        const bool last = (t == Tz - 1);
        const u32 cur = (t & 1) ? OA1 : OA0;
        const u32 nxt = (t & 1) ? OA0 : OA1;
        // prefetch x(t+1)
        float4 xv0, xv1;
        if (!last && xact) {
            xv0 = *(const float4*)(xrowp + (size_t)(t + 1) * Sz * 16);
            xv1 = *(const float4*)(xrowp + (size_t)(t + 1) * Sz * 16 + 4);
        }
        // snapshot both mtiles of A
        uint4 ah0[9], ah1[9];
        {
            const char* a0 = sm + cur + wm * 4608 + lane * 16;
            const char* a1 = a0 + 2 * 4608;
            #pragma unroll
            for (int ks = 0; ks < 9; ks++) {
                ah0[ks] = *(const uint4*)(a0 + ks * 512);
                ah1[ks] = *(const uint4*)(a1 + ks * 512);
            }
        }

        #pragma unroll
        for (int nf = 0; nf < 15; nf++) {
            const int nfg = nh * 15 + nf;
            const char* Bn = Bp + nfg * 2560;
            float a0[4] = {0.f, 0.f, 0.f, 0.f};
            float a1[4] = {0.f, 0.f, 0.f, 0.f};
            #pragma unroll
            for (int kp = 0; kp < 4; kp++) {
                uint4 bb = *(const uint4*)(Bn + kp * 16);
                MMAOP(a0, ah0[2*kp],     bb.x, bb.y);
                MMAOP(a1, ah1[2*kp],     bb.x, bb.y);
                MMAOP(a0, ah0[2*kp + 1], bb.z, bb.w);
                MMAOP(a1, ah1[2*kp + 1], bb.z, bb.w);
            }
            {
                uint2 b8 = *(const uint2*)(Bn + 64);
                MMAOP(a0, ah0[8], b8.x, b8.y);
                MMAOP(a1, ah1[8], b8.x, b8.y);
            }
            // ---- half2 epilogue: pack (m0, m1) per gate column ----
            float2 bv = *(const float2*)(bias + nfg * 8 + 2 * q);
            __half2 bx = __float2half2_rn(bv.x);
            __half2 by = __float2half2_rn(bv.y);
            // pk[j]: col-biased, low=m0, high=m1
            __half2 pk0 = __hadd2(__floats2half2_rn(a0[0], a1[0]), bx);
            __half2 pk1 = __hadd2(__floats2half2_rn(a0[1], a1[1]), by);
            __half2 pk2 = __hadd2(__floats2half2_rn(a0[2], a1[2]), bx);
            __half2 pk3 = __hadd2(__floats2half2_rn(a0[3], a1[3]), by);
            u32 s0 = __shfl_xor_sync(~0u, h2raw(even ? pk2 : pk0), 1);
            u32 s1 = __shfl_xor_sync(~0u, h2raw(even ? pk3 : pk1), 1);
            __half2 pi = even ? pk0 : raw2h(s0);
            __half2 pf = even ? pk1 : raw2h(s1);
            __half2 pg = even ? raw2h(s0) : pk2;
            __half2 po = even ? raw2h(s1) : pk3;
            __half2 si = __hfma2(tanh2(__hmul2(pi, c05)), c05, c05);
            __half2 sf = __hfma2(tanh2(__hmul2(pf, c05)), c05, c05);
            __half2 sg = tanh2(pg);
            __half2 so = __hfma2(tanh2(__hmul2(po, c05)), c05, c05);
            __half2 cc = __hfma2(sf, cst2[nf], __hmul2(si, sg));
            cst2[nf] = cc;
            __half2 hh2 = __hmul2(so, tanh2(cc));
            const int cidx = nfg * 2 + (q >> 1);   // cell 0..119
            const int k = 16 + cidx;
            if (last) {
                sacc0 = fmaf(__low2float(hh2),  wl[cidx], sacc0);
                sacc1 = fmaf(__high2float(hh2), wl[cidx], sacc1);
            } else {
                u32 hv = h2raw(hh2);
                u32 offbase = (u32)((rq * 4 + ((k & 7) >> 1)) * 16 +
                                    (((k >> 3) & 1) * 2 + (q & 1)) * 4 + (k & 1) * 2) +
                              (u32)((k >> 4) * 512);
                u32 off0 = nxt + (u32)((wm + 0) * 9 * 512) + offbase;
                u32 off1 = nxt + (u32)((wm + 2) * 9 * 512) + offbase;
                *(u16*)(sm + off0) = (u16)hv;
                *(u16*)(sm + off1) = (u16)(hv >> 16);
            }
        }
        if (!last && xact) write_x(sm, nxt, tid, xv0, xv1);
        __syncthreads();   // all reads of cur + writes of nxt complete
    }

    sacc0 += __shfl_xor_sync(~0u, sacc0, 2);
    sacc1 += __shfl_xor_sync(~0u, sacc1, 2);
    if (q < 2) {
        int slab = nh * 6400;
        int rbase = row0 + rq + (q & 1) * 8;
        g_spart[slab + rbase + (wm + 0) * 16] = sacc0;
        g_spart[slab + rbase + (wm + 2) * 16] = sacc1;
    }
}

// ---------------- NeuralSort + softmax ----------------
__global__ void sort_kernel(const float* __restrict__ b_lin) {
    __shared__ float s_sm[Sz], rs_sm[Sz];
    int b = blockIdx.x, tid = threadIdx.x;
    if (tid < Sz) {
        int row = b * Sz + tid;
        s_sm[tid] = g_spart[row] + g_spart[6400 + row] + g_spart[2 * 6400 + row]
                  + g_spart[3 * 6400 + row] + b_lin[0];
    }
    __syncthreads();
    if (tid < Sz) {
        float si = s_sm[tid], sum = 0.f;
        for (int j = 0; j < Sz; j++) sum += fabsf(si - s_sm[j]);
        rs_sm[tid] = sum;
    }
    __syncthreads();
    int warp = tid >> 5, lane = tid & 31;
    for (int i = warp; i < Sz; i += 4) {
        float scal = (float)(Sz - 1 - 2 * i);
        float v[4], e[4], mx = -INFINITY;
        #pragma unroll
        for (int c = 0; c < 4; c++) {
            int j = lane + 32 * c;
            v[c] = (j < Sz) ? (s_sm[j] * scal - rs_sm[j]) * 0.2f : -INFINITY;
            mx = fmaxf(mx, v[c]);
        }
        #pragma unroll
        for (int o = 16; o; o >>= 1) mx = fmaxf(mx, __shfl_xor_sync(~0u, mx, o));
        float sum = 0.f;
        #pragma unroll
        for (int c = 0; c < 4; c++) {
            int j = lane + 32 * c;
            e[c] = (j < Sz) ? __expf(v[c] - mx) : 0.f;
            sum += e[c];
        }
        #pragma unroll
        for (int o = 16; o; o >>= 1) sum += __shfl_xor_sync(~0u, sum, o);
        float inv = __fdividef(1.f, sum);
        #pragma unroll
        for (int c = 0; c < 4; c++) {
            int j = lane + 32 * c;
            if (j < Sz) g_foo[(size_t)b * (Sz * Sz) + i * Sz + j] = e[c] * inv;
        }
    }
}

// ---------------- MLP1 K-split GEMM ----------------
__global__ void __launch_bounds__(256) mlp1_kernel() {
    int c = blockIdx.x, tid = threadIdx.x;
    int k0 = c * KCH, kend = k0 + KCH;
    int bg = tid >> 5, og = tid & 31;
    float acc[8][8];
    #pragma unroll
    for (int i = 0; i < 8; i++)
        #pragma unroll
        for (int j = 0; j < 8; j++) acc[i][j] = 0.f;
    const float* fooB = g_foo + (size_t)(bg * 8) * 10000;
    for (int k = k0; k < kend; ++k) {
        float a[8];
        #pragma unroll
        for (int i = 0; i < 8; i++) a[i] = fooB[(size_t)i * 10000 + k];
        float4 w0 = *(const float4*)(g_W2t + (size_t)k * 256 + og * 8);
        float4 w1 = *(const float4*)(g_W2t + (size_t)k * 256 + og * 8 + 4);
        float wv[8] = {w0.x, w0.y, w0.z, w0.w, w1.x, w1.y, w1.z, w1.w};
        #pragma unroll
        for (int i = 0; i < 8; i++)
            #pragma unroll
            for (int j = 0; j < 8; j++) acc[i][j] = fmaf(a[i], wv[j], acc[i][j]);
    }
    #pragma unroll
    for (int i = 0; i < 8; i++)
        #pragma unroll
        for (int j = 0; j < 8; j++)
            g_part[((size_t)c * 64 + bg * 8 + i) * 256 + og * 8 + j] = acc[i][j];
}

// ---------------- two-stage reduce + relu ----------------
__global__ void reduce1_kernel() {
    int b = blockIdx.x, cg = blockIdx.y, o = threadIdx.x;
    float s = 0.f;
    #pragma unroll 5
    for (int c = cg * 25; c < cg * 25 + 25; ++c)
        s += g_part[((size_t)c * 64 + b) * 256 + o];
    g_part2[((size_t)cg * 64 + b) * 256 + o] = s;
}
__global__ void reduce2_kernel(const float* __restrict__ b2) {
    int b = blockIdx.x, o = threadIdx.x;
    float s = b2[o];
    #pragma unroll
    for (int g = 0; g < 10; ++g) s += g_part2[((size_t)g * 64 + b) * 256 + o];
    g_z1[b * 256 + o] = fmaxf(s, 0.f);
}

__global__ void mlp2_kernel(const float* __restrict__ W3, const float* __restrict__ b3,
                            float* __restrict__ out) {
    __shared__ float z1s[256], zs[Sz], s_mx, s_sum;
    int b = blockIdx.x, tid = threadIdx.x;
    z1s[tid] = g_z1[b * 256 + tid];
    z1s[tid + 128] = g_z1[b * 256 + tid + 128];
    __syncthreads();
    if (tid < Sz) {
        float a = b3[tid];
        const float* wr = W3 + tid * 256;
        #pragma unroll 4
        for (int k = 0; k < 256; k++) a = fmaf(z1s[k], wr[k], a);
        zs[tid] = a;
    }
    __syncthreads();
    if (tid == 0) {
        float mx = -INFINITY;
        for (int j = 0; j < Sz; j++) mx = fmaxf(mx, zs[j]);
        float sum = 0.f;
        for (int j = 0; j < Sz; j++) sum += __expf(zs[j] - mx);
        s_mx = mx; s_sum = sum;
    }
    __syncthreads();
    if (tid < Sz) out[b * Sz + tid] = __expf(zs[tid] - s_mx) * __fdividef(1.f, s_sum);
}

extern "C" void kernel_launch(void* const* d_in, const int* in_sizes, int n_in,
                              void* d_out, int out_size) {
    const float* x    = (const float*)d_in[0];
    const float* Wih  = (const float*)d_in[1];
    const float* Whh  = (const float*)d_in[2];
    const float* bih  = (const float*)d_in[3];
    const float* bhh  = (const float*)d_in[4];
    const float* wlin = (const float*)d_in[5];
    const float* blin = (const float*)d_in[6];
    const float* W2   = (const float*)d_in[7];
    const float* b2   = (const float*)d_in[8];
    const float* W3   = (const float*)d_in[9];
    const float* b3   = (const float*)d_in[10];
    float* out = (float*)d_out;
    (void)in_sizes; (void)n_in; (void)out_size;

    cudaFuncSetAttribute(lstm_mma, cudaFuncAttributeMaxDynamicSharedMemorySize, SMEMT);
    prep_kernel<<<256, 256>>>(Wih, Whh, bih, bhh);
    w2t_kernel<<<dim3(313, 8), dim3(32, 32)>>>(W2);
    lstm_mma<<<100, 256, SMEMT>>>(x, wlin);
    sort_kernel<<<Bz, 128>>>(blin);
    mlp1_kernel<<<NCHUNK, 256>>>();
    reduce1_kernel<<<dim3(Bz, 10), 256>>>();
    reduce2_kernel<<<Bz, 256>>>(b2);
    mlp2_kernel<<<Bz, 128>>>(W3, b3, out);
}

// round 16
// speedup vs baseline: 1.2610x; 1.2610x over previous
#include <cuda_runtime.h>
#include <cuda_fp16.h>
#include <math.h>

#define Bz 64
#define Tz 128
#define Sz 100
typedef unsigned int u32; typedef unsigned short u16;

// ---- LSTM mma config (fp16, 48-row CTAs, 134 CTAs, 12 warps, 3-mtile reuse) ----
#define OB 0                 // B image: 480 n * 320B = 153600
#define OA0 153600           // A buf0: 3 mtile * 9 ks * 512B = 13824
#define OA1 167424           // A buf1
#define OBIAS 181248         // 480 floats
#define OWL 183168           // 120 floats
#define SMEMT 183680
#define ABUF 13824
#define NTHL 384
#define NCTA 134
// MLP1
#define KCH 40
#define NCHUNK 250

__device__ u16   g_Bpack[480 * 160];       // [n][160] fp16 weights, ks-paired layout
__device__ float g_biasT[480];             // [n] bias per gate col
__device__ float g_W2t[10000 * 256];
__device__ float g_spart[12 * 6400];       // [warp][row]
__device__ float g_foo[Bz * Sz * Sz];
__device__ float g_part[NCHUNK * Bz * 256];
__device__ float g_part2[10 * Bz * 256];
__device__ float g_z1[Bz * 256];

__device__ __forceinline__ float tanh_a(float x){
    float y; asm("tanh.approx.f32 %0, %1;" : "=f"(y) : "f"(x)); return y;
}
__device__ __forceinline__ u16 h2u(float v){
    __half hh = __float2half_rn(v);
    return *reinterpret_cast<u16*>(&hh);
}
#define MMAOP(d, a, b0, b1) asm volatile( \
    "mma.sync.aligned.m16n8k16.row.col.f32.f16.f16.f32 {%0,%1,%2,%3},{%4,%5,%6,%7},{%8,%9},{%0,%1,%2,%3};" \
    : "+f"((d)[0]), "+f"((d)[1]), "+f"((d)[2]), "+f"((d)[3]) \
    : "r"((a).x),"r"((a).y),"r"((a).z),"r"((a).w), "r"(b0),"r"(b1))

// ---------------- prep: B pack (ks-paired) + bias ----------------
__global__ void prep_kernel(const float* __restrict__ Wih, const float* __restrict__ Whh,
                            const float* __restrict__ bih, const float* __restrict__ bhh) {
    int idx = blockIdx.x * blockDim.x + threadIdx.x, stride = gridDim.x * blockDim.x;
    for (int i = idx; i < 480 * 144; i += stride) {
        int k = i % 144, n = i / 144;
        int g = n & 3, c = n >> 2;           // cell 0..119
        int j = g * 120 + c;
        float v = 0.f;
        if (k < 16) v = Wih[j * 16 + k];
        else if (k < 136) v = Whh[j * 120 + (k - 16)];
        int ks = k >> 4, kl = k & 15;
        int q = (kl & 7) >> 1;
        int pos = q * 40 + (ks >> 1) * 8 + (ks & 1) * 4 + ((kl >> 3) & 1) * 2 + (kl & 1);
        g_Bpack[(size_t)n * 160 + pos] = h2u(v);
    }
    for (int i = idx; i < 480; i += stride) {
        int j = (i & 3) * 120 + (i >> 2);
        g_biasT[i] = bih[j] + bhh[j];
    }
}

// ---------------- W2 transpose, smem-tiled ----------------
__global__ void w2t_kernel(const float* __restrict__ W2) {
    __shared__ float tile[32][33];
    int k0 = blockIdx.x * 32, o0 = blockIdx.y * 32;
    int tx = threadIdx.x, ty = threadIdx.y;
    int k = k0 + tx, o = o0 + ty;
    if (k < 10000) tile[ty][tx] = W2[(size_t)o * 10000 + k];
    __syncthreads();
    int kk = k0 + ty, oo = o0 + tx;
    if (kk < 10000) g_W2t[(size_t)kk * 256 + oo] = tile[tx][ty];
}

// ---------------- warp-MMA LSTM (48 rows/CTA, 12 warps, ks-outer) ----------------
__device__ __forceinline__ void write_x(char* sm, u32 abase, int tid, float4 v0, float4 v1) {
    int lr = tid >> 1;                       // row 0..47
    float xv[8] = {v0.x, v0.y, v0.z, v0.w, v1.x, v1.y, v1.z, v1.w};
    u32 base = abase + (u32)((lr >> 4) * 9) * 512;
    #pragma unroll
    for (int j = 0; j < 4; j++) {
        int k = (tid & 1) * 8 + 2 * j;
        u32 off = base + (u32)(((lr & 7) * 4 + ((k & 7) >> 1)) * 16 + (((k >> 3) & 1) * 2 + ((lr >> 3) & 1)) * 4);
        *(u32*)(sm + off) = (u32)h2u(xv[2*j]) | ((u32)h2u(xv[2*j+1]) << 16);
    }
}

__global__ void __launch_bounds__(NTHL, 1)
lstm_mma(const float* __restrict__ x, const float* __restrict__ w_lin) {
    extern __shared__ char sm[];
    const int tid = threadIdx.x, w = tid >> 5, lane = tid & 31;
    const int q = lane & 3, rq = lane >> 2;
    const bool even = !(q & 1);
    const int row0 = blockIdx.x * 48;
    const bool xact = tid < 96;   // 2 threads per row for x staging
    const int lr = tid >> 1;
    int xrow = row0 + (xact ? lr : 0);
    if (xrow > 6399) xrow = 6399;            // tail-CTA clamp (finite garbage)
    const int xb = xrow / Sz, xs = xrow - xb * Sz;
    const float* xrowp = x + ((size_t)xb * Tz * Sz + xs) * 16 + (tid & 1) * 8;

    // init: B copy, A zero (both bufs), bias, w_lin
    {
        const int4* src = (const int4*)g_Bpack;
        int4* dst = (int4*)sm;
        for (int i = tid; i < 153600 / 16; i += NTHL) dst[i] = src[i];
        int4 z = {0, 0, 0, 0};
        for (int i = tid; i < (2 * ABUF) / 16; i += NTHL) ((int4*)(sm + OA0))[i] = z;
        for (int i = tid; i < 480; i += NTHL) ((float*)(sm + OBIAS))[i] = g_biasT[i];
        if (tid < 120) ((float*)(sm + OWL))[tid] = w_lin[tid];
    }
    __syncthreads();
    if (xact) {
        float4 v0 = *(const float4*)(xrowp);
        float4 v1 = *(const float4*)(xrowp + 4);
        write_x(sm, OA0, tid, v0, v1);
    }
    __syncthreads();

    const float* wl = (const float*)(sm + OWL);
    const float* bias = (const float*)(sm + OBIAS);
    const char* Bp = sm + rq * 320 + q * 80;   // n-row 320B, q-stride 80B

    float cst[15];                // [nf*3 + m]
    #pragma unroll
    for (int i = 0; i < 15; i++) cst[i] = 0.f;
    float sacc[3] = {0.f, 0.f, 0.f};

    for (int t = 0; t < Tz; ++t) {
        const bool last = (t == Tz - 1);
        const u32 cur = (t & 1) ? OA1 : OA0;
        const u32 nxt = (t & 1) ? OA0 : OA1;
        // prefetch x(t+1)
        float4 xv0, xv1;
        if (!last && xact) {
            xv0 = *(const float4*)(xrowp + (size_t)(t + 1) * Sz * 16);
            xv1 = *(const float4*)(xrowp + (size_t)(t + 1) * Sz * 16 + 4);
        }

        float acc[5][3][4];
        #pragma unroll
        for (int nf = 0; nf < 5; nf++)
            #pragma unroll
            for (int m = 0; m < 3; m++)
                #pragma unroll
                for (int i = 0; i < 4; i++) acc[nf][m][i] = 0.f;

        const char* Acur = sm + cur + lane * 16;
        // ks-outer: 3 A-frags live, each B-frag feeds 3 MMAs
        #pragma unroll
        for (int ks = 0; ks < 9; ks++) {
            uint4 a0 = *(const uint4*)(Acur + 0 * 4608 + ks * 512);
            uint4 a1 = *(const uint4*)(Acur + 1 * 4608 + ks * 512);
            uint4 a2 = *(const uint4*)(Acur + 2 * 4608 + ks * 512);
            const char* Bk = Bp + (ks >> 1) * 16 + (ks & 1) * 8;
            #pragma unroll
            for (int nf = 0; nf < 5; nf++) {
                uint2 bb = *(const uint2*)(Bk + (w * 5 + nf) * 2560);
                MMAOP(acc[nf][0], a0, bb.x, bb.y);
                MMAOP(acc[nf][1], a1, bb.x, bb.y);
                MMAOP(acc[nf][2], a2, bb.x, bb.y);
            }
        }

        #pragma unroll
        for (int nf = 0; nf < 5; nf++) {
            const int nfg = w * 5 + nf;
            float2 bv = *(const float2*)(bias + nfg * 8 + 2 * q);
            const int cidx = nfg * 2 + (q >> 1);   // cell 0..119
            const int k = 16 + cidx;
            #pragma unroll
            for (int m = 0; m < 3; m++) {
                float* aa = acc[nf][m];
                float d0 = aa[0] + bv.x;
                float d1 = aa[1] + bv.y;
                float d2 = aa[2] + bv.x;
                float d3 = aa[3] + bv.y;
                float s0 = __shfl_xor_sync(~0u, even ? d2 : d0, 1);
                float s1 = __shfl_xor_sync(~0u, even ? d3 : d1, 1);
                float gi = even ? d0 : s0;
                float gf = even ? d1 : s1;
                float gg = even ? s0 : d2;
                float go = even ? s1 : d3;
                float si = fmaf(tanh_a(0.5f * gi), 0.5f, 0.5f);
                float sf = fmaf(tanh_a(0.5f * gf), 0.5f, 0.5f);
                float sg = tanh_a(gg);
                float so = fmaf(tanh_a(0.5f * go), 0.5f, 0.5f);
                float cc = fmaf(sf, cst[nf * 3 + m], si * sg);
                cst[nf * 3 + m] = cc;
                float h = so * tanh_a(cc);
                if (last) {
                    sacc[m] = fmaf(h, wl[cidx], sacc[m]);
                } else {
                    u32 off = nxt + (u32)((m * 9 + (k >> 4)) * 512) +
                              (u32)((rq * 4 + ((k & 7) >> 1)) * 16 +
                                    (((k >> 3) & 1) * 2 + (q & 1)) * 4 + (k & 1) * 2);
                    *(u16*)(sm + off) = h2u(h);
                }
            }
        }
        if (!last && xact) write_x(sm, nxt, tid, xv0, xv1);
        __syncthreads();   // all reads of cur + writes of nxt complete
    }

    #pragma unroll
    for (int m = 0; m < 3; m++)
        sacc[m] += __shfl_xor_sync(~0u, sacc[m], 2);
    if (q < 2) {
        #pragma unroll
        for (int m = 0; m < 3; m++) {
            int row = row0 + m * 16 + rq + (q & 1) * 8;
            if (row < 6400) g_spart[w * 6400 + row] = sacc[m];
        }
    }
}

// ---------------- NeuralSort + softmax ----------------
__global__ void sort_kernel(const float* __restrict__ b_lin) {
    __shared__ float s_sm[Sz], rs_sm[Sz];
    int b = blockIdx.x, tid = threadIdx.x;
    if (tid < Sz) {
        int row = b * Sz + tid;
        float s = b_lin[0];
        #pragma unroll
        for (int g = 0; g < 12; g++) s += g_spart[g * 6400 + row];
        s_sm[tid] = s;
    }
    __syncthreads();
    if (tid < Sz) {
        float si = s_sm[tid], sum = 0.f;
        for (int j = 0; j < Sz; j++) sum += fabsf(si - s_sm[j]);
        rs_sm[tid] = sum;
    }
    __syncthreads();
    int warp = tid >> 5, lane = tid & 31;
    for (int i = warp; i < Sz; i += 8) {
        float scal = (float)(Sz - 1 - 2 * i);
        float v[4], e[4], mx = -INFINITY;
        #pragma unroll
        for (int c = 0; c < 4; c++) {
            int j = lane + 32 * c;
            v[c] = (j < Sz) ? (s_sm[j] * scal - rs_sm[j]) * 0.2f : -INFINITY;
            mx = fmaxf(mx, v[c]);
        }
        #pragma unroll
        for (int o = 16; o; o >>= 1) mx = fmaxf(mx, __shfl_xor_sync(~0u, mx, o));
        float sum = 0.f;
        #pragma unroll
        for (int c = 0; c < 4; c++) {
            int j = lane + 32 * c;
            e[c] = (j < Sz) ? __expf(v[c] - mx) : 0.f;
            sum += e[c];
        }
        #pragma unroll
        for (int o = 16; o; o >>= 1) sum += __shfl_xor_sync(~0u, sum, o);
        float inv = __fdividef(1.f, sum);
        #pragma unroll
        for (int c = 0; c < 4; c++) {
            int j = lane + 32 * c;
            if (j < Sz) g_foo[(size_t)b * (Sz * Sz) + i * Sz + j] = e[c] * inv;
        }
    }
}

// ---------------- MLP1 K-split GEMM (smem-staged foo) ----------------
__global__ void __launch_bounds__(256) mlp1_kernel() {
    __shared__ float fooS[KCH * 64];
    int c = blockIdx.x, tid = threadIdx.x;
    int k0 = c * KCH;
    for (int idx = tid; idx < KCH * 64; idx += 256) {
        int b = idx / KCH, kk = idx - b * KCH;
        fooS[kk * 64 + b] = g_foo[(size_t)b * 10000 + k0 + kk];
    }
    __syncthreads();
    int bg = tid >> 5, og = tid & 31;
    float acc[8][8];
    #pragma unroll
    for (int i = 0; i < 8; i++)
        #pragma unroll
        for (int j = 0; j < 8; j++) acc[i][j] = 0.f;
    for (int kk = 0; kk < KCH; ++kk) {
        const float* fr = fooS + kk * 64 + bg * 8;
        float4 A0 = *(const float4*)fr;
        float4 A1 = *(const float4*)(fr + 4);
        float a[8] = {A0.x, A0.y, A0.z, A0.w, A1.x, A1.y, A1.z, A1.w};
        const float* wp = g_W2t + (size_t)(k0 + kk) * 256 + og * 8;
        float4 w0 = *(const float4*)wp;
        float4 w1 = *(const float4*)(wp + 4);
        float wv[8] = {w0.x, w0.y, w0.z, w0.w, w1.x, w1.y, w1.z, w1.w};
        #pragma unroll
        for (int i = 0; i < 8; i++)
            #pragma unroll
            for (int j = 0; j < 8; j++) acc[i][j] = fmaf(a[i], wv[j], acc[i][j]);
    }
    #pragma unroll
    for (int i = 0; i < 8; i++)
        #pragma unroll
        for (int j = 0; j < 8; j++)
            g_part[((size_t)c * 64 + bg * 8 + i) * 256 + og * 8 + j] = acc[i][j];
}

// ---------------- two-stage reduce + relu ----------------
__global__ void reduce1_kernel() {
    int b = blockIdx.x, cg = blockIdx.y, o = threadIdx.x;
    float s = 0.f;
    #pragma unroll 5
    for (int c = cg * 25; c < cg * 25 + 25; ++c)
        s += g_part[((size_t)c * 64 + b) * 256 + o];
    g_part2[((size_t)cg * 64 + b) * 256 + o] = s;
}
__global__ void reduce2_kernel(const float* __restrict__ b2) {
    int b = blockIdx.x, o = threadIdx.x;
    float s = b2[o];
    #pragma unroll
    for (int g = 0; g < 10; ++g) s += g_part2[((size_t)g * 64 + b) * 256 + o];
    g_z1[b * 256 + o] = fmaxf(s, 0.f);
}

__global__ void mlp2_kernel(const float* __restrict__ W3, const float* __restrict__ b3,
                            float* __restrict__ out) {
    __shared__ float z1s[256], zs[Sz], s_mx, s_sum;
    int b = blockIdx.x, tid = threadIdx.x;
    z1s[tid] = g_z1[b * 256 + tid];
    z1s[tid + 128] = g_z1[b * 256 + tid + 128];
    __syncthreads();
    if (tid < Sz) {
        float a = b3[tid];
        const float* wr = W3 + tid * 256;
        #pragma unroll 4
        for (int k = 0; k < 256; k++) a = fmaf(z1s[k], wr[k], a);
        zs[tid] = a;
    }
    __syncthreads();
    if (tid == 0) {
        float mx = -INFINITY;
        for (int j = 0; j < Sz; j++) mx = fmaxf(mx, zs[j]);
        float sum = 0.f;
        for (int j = 0; j < Sz; j++) sum += __expf(zs[j] - mx);
        s_mx = mx; s_sum = sum;
    }
    __syncthreads();
    if (tid < Sz) out[b * Sz + tid] = __expf(zs[tid] - s_mx) * __fdividef(1.f, s_sum);
}

extern "C" void kernel_launch(void* const* d_in, const int* in_sizes, int n_in,
                              void* d_out, int out_size) {
    const float* x    = (const float*)d_in[0];
    const float* Wih  = (const float*)d_in[1];
    const float* Whh  = (const float*)d_in[2];
    const float* bih  = (const float*)d_in[3];
    const float* bhh  = (const float*)d_in[4];
    const float* wlin = (const float*)d_in[5];
    const float* blin = (const float*)d_in[6];
    const float* W2   = (const float*)d_in[7];
    const float* b2   = (const float*)d_in[8];
    const float* W3   = (const float*)d_in[9];
    const float* b3   = (const float*)d_in[10];
    float* out = (float*)d_out;
    (void)in_sizes; (void)n_in; (void)out_size;

    cudaFuncSetAttribute(lstm_mma, cudaFuncAttributeMaxDynamicSharedMemorySize, SMEMT);
    prep_kernel<<<256, 256>>>(Wih, Whh, bih, bhh);
    w2t_kernel<<<dim3(313, 8), dim3(32, 32)>>>(W2);
    lstm_mma<<<NCTA, NTHL, SMEMT>>>(x, wlin);
    sort_kernel<<<Bz, 256>>>(blin);
    mlp1_kernel<<<NCHUNK, 256>>>();
    reduce1_kernel<<<dim3(Bz, 10), 256>>>();
    reduce2_kernel<<<Bz, 256>>>(b2);
    mlp2_kernel<<<Bz, 128>>>(W3, b3, out);
}